// round 10
// baseline (speedup 1.0000x reference)
#include <cuda_runtime.h>
#include <cstdint>

#define BATCH 512
#define TSTEPS 1024
#define IDIM 64
#define HDIM 128
#define NROW 4                             // batch rows per CTA

typedef unsigned long long u64t;

__device__ __forceinline__ u64t ffma2(u64t a, u64t b, u64t c) {
    u64t d;
    asm("fma.rn.f32x2 %0, %1, %2, %3;" : "=l"(d) : "l"(a), "l"(b), "l"(c));
    return d;
}
__device__ __forceinline__ u64t fmul2(u64t a, u64t b) {
    u64t d;
    asm("mul.rn.f32x2 %0, %1, %2;" : "=l"(d) : "l"(a), "l"(b));
    return d;
}
__device__ __forceinline__ u64t pk(float a, float b) {
    u64t r; asm("mov.b64 %0, {%1, %2};" : "=l"(r) : "f"(a), "f"(b)); return r;
}
__device__ __forceinline__ float hadd2(u64t v) {
    float x, y;
    asm("mov.b64 {%0, %1}, %2;" : "=f"(x), "=f"(y) : "l"(v));
    return x + y;
}
__device__ __forceinline__ float tanh_ap(float x) {
    float y; asm("tanh.approx.f32 %0, %1;" : "=f"(y) : "f"(x)); return y;
}

// ---------------------------------------------------------------------------
// Fully fused RNN: 128 CTAs x 256 threads, 4 batch rows/CTA, 1 CTA/SM.
// Thread tiling: lane=(kq=lane>>3, jl=lane&7); warp w -> j0=w*16+jl, j1=j0+8.
// Per thread per step: 2j x 4b x 32k hh-FMAs (128 ffma2) + 2j x 4b x 16i
// x-FMAs (64 ffma2), butterfly reduce (6 shfl, each lane finishes 2 (j,b)),
// 2 tanh + 2 STS.
// SPLIT BARRIER: after STS h_t each thread bar.arrive's (non-blocking),
// computes next step's x-projection partials (no h dependency) while the
// barrier drains, then bar.sync's. Expected count = 512 (256 threads x
// arrive+sync) — moves 1/3 of the FMA work into the former barrier-wait.
// ---------------------------------------------------------------------------

#define HSTR 144                             // padded h row stride (floats)
#define XROW 80                              // padded x row (floats)
#define SX_B_STRIDE (16 * XROW)              // 1280 floats per batch per buf
#define SX_BUF_BYTES (NROW * 16 * XROW * 4)  // 20480

#define BAR_ARRIVE() asm volatile("bar.arrive 1, 512;" ::: "memory")
#define BAR_SYNC()   asm volatile("bar.sync 1, 512;" ::: "memory")

struct Ctx {
    u64t whh[2][16];   // [jj][2c+p]  k = 32kq + 4c + {0..3}
    u64t wih[2][8];    // [jj][2cc+p] i = 16kq + 4cc + {0..3}
    int  kq36, kq20;
    int  stoff0, stoff1;   // final h store offsets (2 batches, same j)
    float biasF;           // bias of this lane's final j
    bool odd1, odd2;       // kq&1, kq&2 (butterfly select bits)
};

// Seed accumulators with x-projection partials for one step (no h dep).
__device__ __forceinline__ void xseed(const Ctx& C,
                                      const float* __restrict__ xn,
                                      u64t (&acc)[2][4])
{
    const float* xq = xn + C.kq20;
    #pragma unroll
    for (int b = 0; b < 4; b++) {
        const float* xb = xq + b * SX_B_STRIDE;
        ulonglong2 va = *(const ulonglong2*)(xb);
        ulonglong2 vb = *(const ulonglong2*)(xb + 4);
        ulonglong2 vc = *(const ulonglong2*)(xb + 8);
        ulonglong2 vd = *(const ulonglong2*)(xb + 12);
        acc[0][b] = fmul2(va.x, C.wih[0][0]);
        acc[1][b] = fmul2(va.x, C.wih[1][0]);
        acc[0][b] = ffma2(va.y, C.wih[0][1], acc[0][b]);
        acc[1][b] = ffma2(va.y, C.wih[1][1], acc[1][b]);
        acc[0][b] = ffma2(vb.x, C.wih[0][2], acc[0][b]);
        acc[1][b] = ffma2(vb.x, C.wih[1][2], acc[1][b]);
        acc[0][b] = ffma2(vb.y, C.wih[0][3], acc[0][b]);
        acc[1][b] = ffma2(vb.y, C.wih[1][3], acc[1][b]);
        acc[0][b] = ffma2(vc.x, C.wih[0][4], acc[0][b]);
        acc[1][b] = ffma2(vc.x, C.wih[1][4], acc[1][b]);
        acc[0][b] = ffma2(vc.y, C.wih[0][5], acc[0][b]);
        acc[1][b] = ffma2(vc.y, C.wih[1][5], acc[1][b]);
        acc[0][b] = ffma2(vd.x, C.wih[0][6], acc[0][b]);
        acc[1][b] = ffma2(vd.x, C.wih[1][6], acc[1][b]);
        acc[0][b] = ffma2(vd.y, C.wih[0][7], acc[0][b]);
        acc[1][b] = ffma2(vd.y, C.wih[1][7], acc[1][b]);
    }
}

// h-FMAs + butterfly reduce + tanh + STS (no barrier inside).
__device__ __forceinline__ void hstep(const Ctx& C,
                                      const float* __restrict__ hr,
                                      float* __restrict__ hw,
                                      u64t (&acc)[2][4])
{
    const float* h0 = hr + C.kq36;
    #pragma unroll
    for (int c = 0; c < 8; c++) {
        #pragma unroll
        for (int b = 0; b < 4; b++) {
            ulonglong2 hv = *(const ulonglong2*)(h0 + b * HSTR + 4 * c);
            acc[0][b] = ffma2(hv.x, C.whh[0][2 * c],     acc[0][b]);
            acc[1][b] = ffma2(hv.x, C.whh[1][2 * c],     acc[1][b]);
            acc[0][b] = ffma2(hv.y, C.whh[0][2 * c + 1], acc[0][b]);
            acc[1][b] = ffma2(hv.y, C.whh[1][2 * c + 1], acc[1][b]);
        }
    }

    float s[2][4];
    #pragma unroll
    for (int jj = 0; jj < 2; jj++)
        #pragma unroll
        for (int b = 0; b < 4; b++) s[jj][b] = hadd2(acc[jj][b]);

    // round 1 (xor 8): keep batches with (b&1)==(kq&1)
    float u[2][2];
    #pragma unroll
    for (int jj = 0; jj < 2; jj++) {
        float gl = C.odd1 ? s[jj][0] : s[jj][1];
        float gh = C.odd1 ? s[jj][2] : s[jj][3];
        float rl = __shfl_xor_sync(0xffffffffu, gl, 8);
        float rh = __shfl_xor_sync(0xffffffffu, gh, 8);
        u[jj][0] = (C.odd1 ? s[jj][1] : s[jj][0]) + rl;   // batch kq&1
        u[jj][1] = (C.odd1 ? s[jj][3] : s[jj][2]) + rh;   // batch (kq&1)+2
    }
    // round 2 (xor 16): keep j = odd2 ? j1 : j0
    float g0 = C.odd2 ? u[0][0] : u[1][0];
    float g1 = C.odd2 ? u[0][1] : u[1][1];
    float r0 = __shfl_xor_sync(0xffffffffu, g0, 16);
    float r1 = __shfl_xor_sync(0xffffffffu, g1, 16);
    float f0 = (C.odd2 ? u[1][0] : u[0][0]) + r0;
    float f1 = (C.odd2 ? u[1][1] : u[0][1]) + r1;

    hw[C.stoff0] = tanh_ap(f0 + C.biasF);
    hw[C.stoff1] = tanh_ap(f1 + C.biasF);
}

// Stage one 16-step x tile via cp.async (addresses recomputed, not cached).
__device__ __forceinline__ void stage_tile(
    const float* __restrict__ xg, int row0, int tid, unsigned sx0,
    int sbuf, int tile)
{
    #pragma unroll
    for (int r = 0; r < 4; r++) {
        int idx = tid + 256 * r;          // 0..1023
        int bb  = idx >> 8;               // batch within CTA
        int rem = idx & 255;
        int tt  = rem >> 4, f4 = rem & 15;
        const float* src = xg + ((size_t)(row0 + bb) * TSTEPS + tile * 16 + tt) * IDIM + f4 * 4;
        unsigned dst = sx0 + (unsigned)sbuf * SX_BUF_BYTES
                     + (unsigned)(bb * SX_B_STRIDE + tt * XROW + (f4 >> 2) * 20 + (f4 & 3) * 4) * 4u;
        asm volatile("cp.async.cg.shared.global [%0], [%1], 16;"
                     :: "r"(dst), "l"(src) : "memory");
    }
}

__global__ void __launch_bounds__(256, 1) rnn_fused(
    const float* __restrict__ x,
    const float* __restrict__ W_ih,
    const float* __restrict__ W_hh,
    const float* __restrict__ b_ih,
    const float* __restrict__ b_hh,
    const float* __restrict__ fc_w,
    const float* __restrict__ fc_b,
    float* __restrict__ out)
{
    __shared__ __align__(16) float sx[2][NROW][16][XROW];   // 40 KB
    __shared__ __align__(16) float hbuf[2][NROW][HSTR];     // 4.5 KB

    const int tid  = threadIdx.x;
    const int warp = tid >> 5, lane = tid & 31;
    const int kq   = lane >> 3;
    const int jl   = lane & 7;
    const int j0   = warp * 16 + jl;
    const int j1   = j0 + 8;
    const int row0 = blockIdx.x * NROW;

    Ctx C;
    C.kq36 = 36 * kq;
    C.kq20 = 20 * kq;
    C.odd1 = (kq & 1) != 0;
    C.odd2 = (kq & 2) != 0;
    {
        int jfin = C.odd2 ? j1 : j0;
        int jfp  = jfin + ((jfin >> 5) << 2);
        int kb0  = kq & 1;
        C.stoff0 = kb0 * HSTR + jfp;
        C.stoff1 = (kb0 + 2) * HSTR + jfp;
        C.biasF  = b_ih[jfin] + b_hh[jfin];
    }

    // ---- load weights into registers ----
    #pragma unroll
    for (int jj = 0; jj < 2; jj++) {
        const float4* wr = (const float4*)(W_hh + (size_t)(jj ? j1 : j0) * HDIM + 32 * kq);
        #pragma unroll
        for (int c = 0; c < 8; c++) {
            float4 v = __ldg(wr + c);
            C.whh[jj][2 * c]     = pk(v.x, v.y);
            C.whh[jj][2 * c + 1] = pk(v.z, v.w);
        }
    }
    #pragma unroll
    for (int jj = 0; jj < 2; jj++) {
        const float4* wr = (const float4*)(W_ih + (size_t)(jj ? j1 : j0) * IDIM + 16 * kq);
        #pragma unroll
        for (int cc = 0; cc < 4; cc++) {
            float4 v = __ldg(wr + cc);
            C.wih[jj][2 * cc]     = pk(v.x, v.y);
            C.wih[jj][2 * cc + 1] = pk(v.z, v.w);
        }
    }

    // ---- zero h buffers ----
    for (int i = tid; i < 2 * NROW * HSTR; i += 256) (&hbuf[0][0][0])[i] = 0.f;

    const unsigned sx0 = (unsigned)__cvta_generic_to_shared(&sx[0][0][0][0]);

    // stage tile 0 into buffer 0
    stage_tile(x, row0, tid, sx0, 0, 0);
    asm volatile("cp.async.commit_group;" ::: "memory");
    asm volatile("cp.async.wait_group 0;" ::: "memory");
    __syncthreads();

    u64t acc[2][4];
    xseed(C, &sx[0][0][0][0], acc);   // x partials for t = 0

    float* hr = &hbuf[0][0][0];
    float* hw = &hbuf[1][0][0];

    int s = 0;
    #pragma unroll 1
    for (int tile = 0; tile < TSTEPS / 16; tile++) {
        if (tile + 1 < TSTEPS / 16)
            stage_tile(x, row0, tid, sx0, s ^ 1, tile + 1);
        asm volatile("cp.async.commit_group;" ::: "memory");

        const float* xb = &sx[s][0][0][0];

        // steps 0..14: xseed(t+1) overlapped with the barrier drain
        #pragma unroll 1
        for (int u = 0; u < 15; u++) {
            hstep(C, hr, hw, acc);
            BAR_ARRIVE();
            xseed(C, xb + (u + 1) * XROW, acc);
            BAR_SYNC();
            float* t = hr; hr = hw; hw = t;
        }
        // step 15: next x lives in the other buffer — wait for cp.async,
        // then sync BEFORE reading it (other threads' async stores).
        hstep(C, hr, hw, acc);
        asm volatile("cp.async.wait_group 0;" ::: "memory");
        BAR_ARRIVE();
        BAR_SYNC();
        if (tile + 1 < TSTEPS / 16)
            xseed(C, &sx[s ^ 1][0][0][0], acc);
        { float* t = hr; hr = hw; hw = t; }
        s ^= 1;
    }

    // 1024 steps (even) -> final h in hbuf[0]
    if (warp < NROW) {
        const int b = warp;
        float sum = 0.f;
        #pragma unroll
        for (int i = lane; i < HDIM; i += 32)
            sum += hbuf[0][b][i + ((i >> 5) << 2)] * fc_w[i];
        #pragma unroll
        for (int o = 16; o > 0; o >>= 1) sum += __shfl_xor_sync(0xffffffffu, sum, o);
        if (lane == 0) out[row0 + b] = 1.f / (1.f + __expf(-(sum + fc_b[0])));
    }
}

// ---------------------------------------------------------------------------
extern "C" void kernel_launch(void* const* d_in, const int* in_sizes, int n_in,
                              void* d_out, int out_size)
{
    const float* x    = (const float*)d_in[0];
    const float* W_ih = (const float*)d_in[1];
    const float* W_hh = (const float*)d_in[2];
    const float* b_ih = (const float*)d_in[3];
    const float* b_hh = (const float*)d_in[4];
    const float* fc_w = (const float*)d_in[5];
    const float* fc_b = (const float*)d_in[6];
    float* out = (float*)d_out;

    rnn_fused<<<BATCH / NROW, 256>>>(x, W_ih, W_hh, b_ih, b_hh, fc_w, fc_b, out);
}

// round 11
// speedup vs baseline: 1.1085x; 1.1085x over previous
#include <cuda_runtime.h>
#include <cstdint>

#define BATCH 512
#define TSTEPS 1024
#define IDIM 64
#define HDIM 128

typedef unsigned long long u64t;

__device__ __forceinline__ u64t ffma2(u64t a, u64t b, u64t c) {
    u64t d;
    asm("fma.rn.f32x2 %0, %1, %2, %3;" : "=l"(d) : "l"(a), "l"(b), "l"(c));
    return d;
}
__device__ __forceinline__ u64t fmul2(u64t a, u64t b) {
    u64t d;
    asm("mul.rn.f32x2 %0, %1, %2;" : "=l"(d) : "l"(a), "l"(b));
    return d;
}
__device__ __forceinline__ u64t pk(float a, float b) {
    u64t r; asm("mov.b64 %0, {%1, %2};" : "=l"(r) : "f"(a), "f"(b)); return r;
}
__device__ __forceinline__ float hadd2(u64t v) {
    float x, y;
    asm("mov.b64 {%0, %1}, %2;" : "=f"(x), "=f"(y) : "l"(v));
    return x + y;
}
__device__ __forceinline__ float tanh_ap(float x) {
    float y; asm("tanh.approx.f32 %0, %1;" : "=f"(y) : "f"(x)); return y;
}

// ---------------------------------------------------------------------------
// Fully fused RNN: 256 CTAs x 256 threads, 2 batch rows/CTA, 2 CTAs/SM
// (R8 structure — proven best). One change vs R8:
// SPLIT BARRIER with x-FMA filler. Per step:
//    hstep: 64 hh-ffma2 (acc pre-seeded with this step's x partials)
//           -> butterfly reduce -> tanh -> STS h_t
//    bar.arrive (non-blocking)
//    xseed:  32 x-ffma2 for step t+1 (no h dependency, staged x)
//    bar.sync
// The x-projection third of the FMA work and the ~70cyc STS-drain cost of
// the barrier now overlap, shortening the inter-barrier dependent chain.
// ---------------------------------------------------------------------------

#define HSTR 144                           // padded h row stride (floats)
#define XROW 80                            // padded x row (floats): 4 * 20
#define SX_B_STRIDE (16 * XROW)            // 1280 floats per batch per buffer
#define SX_BUF_BYTES (2 * 16 * XROW * 4)   // 10240

#define BAR_ARRIVE() asm volatile("bar.arrive 1, 512;" ::: "memory")
#define BAR_SYNC()   asm volatile("bar.sync 1, 512;" ::: "memory")

struct StepCtx {
    u64t whh[2][16];   // [jj][2c+p]  k = 32kq + 4c + {0..3}
    u64t wih[2][8];    // [jj][2cc+p] i = 16kq + 4cc + {0..3}
    int  kq36;         // h read offset (36*kq)
    int  kq20;         // x read offset (20*kq)
    int  stoff;        // final h store offset (floats) for this lane
    float biasF;       // bias of this lane's final (j,b)
    bool odd1, odd2;   // kq&1, kq&2 (butterfly select bits)
};

// Seed accumulators with x-projection partials for one step (no h dep).
__device__ __forceinline__ void xseed(const StepCtx& C,
                                      const float* __restrict__ xx,
                                      u64t (&acc)[4])
{
    const float* x0 = xx + C.kq20;
    const float* x1 = x0 + SX_B_STRIDE;
    {
        ulonglong2 v0 = *(const ulonglong2*)(x0);
        ulonglong2 v1 = *(const ulonglong2*)(x1);
        acc[0] = fmul2(v0.x, C.wih[0][0]);
        acc[2] = fmul2(v0.x, C.wih[1][0]);
        acc[1] = fmul2(v1.x, C.wih[0][0]);
        acc[3] = fmul2(v1.x, C.wih[1][0]);
        acc[0] = ffma2(v0.y, C.wih[0][1], acc[0]);
        acc[2] = ffma2(v0.y, C.wih[1][1], acc[2]);
        acc[1] = ffma2(v1.y, C.wih[0][1], acc[1]);
        acc[3] = ffma2(v1.y, C.wih[1][1], acc[3]);
    }
    #pragma unroll
    for (int cc = 1; cc < 4; cc++) {
        ulonglong2 v0 = *(const ulonglong2*)(x0 + 4 * cc);
        ulonglong2 v1 = *(const ulonglong2*)(x1 + 4 * cc);
        acc[0] = ffma2(v0.x, C.wih[0][2 * cc],     acc[0]);
        acc[2] = ffma2(v0.x, C.wih[1][2 * cc],     acc[2]);
        acc[1] = ffma2(v1.x, C.wih[0][2 * cc],     acc[1]);
        acc[3] = ffma2(v1.x, C.wih[1][2 * cc],     acc[3]);
        acc[0] = ffma2(v0.y, C.wih[0][2 * cc + 1], acc[0]);
        acc[2] = ffma2(v0.y, C.wih[1][2 * cc + 1], acc[2]);
        acc[1] = ffma2(v1.y, C.wih[0][2 * cc + 1], acc[1]);
        acc[3] = ffma2(v1.y, C.wih[1][2 * cc + 1], acc[3]);
    }
}

// h-FMAs + butterfly reduce + tanh + STS. No barrier inside; acc consumed.
__device__ __forceinline__ void hstep(
    const StepCtx& C,
    const float* __restrict__ hr,
    float* __restrict__ hw,
    u64t (&acc)[4])
{
    u64t a00 = acc[0], a01 = acc[1], a10 = acc[2], a11 = acc[3];
    const float* hb0 = hr + C.kq36;
    const float* hb1 = hb0 + HSTR;
    #pragma unroll
    for (int c = 0; c < 8; c++) {
        ulonglong2 h0 = *(const ulonglong2*)(hb0 + 4 * c);
        ulonglong2 h1 = *(const ulonglong2*)(hb1 + 4 * c);
        a00 = ffma2(h0.x, C.whh[0][2 * c],     a00);
        a10 = ffma2(h0.x, C.whh[1][2 * c],     a10);
        a00 = ffma2(h0.y, C.whh[0][2 * c + 1], a00);
        a10 = ffma2(h0.y, C.whh[1][2 * c + 1], a10);
        a01 = ffma2(h1.x, C.whh[0][2 * c],     a01);
        a11 = ffma2(h1.x, C.whh[1][2 * c],     a11);
        a01 = ffma2(h1.y, C.whh[0][2 * c + 1], a01);
        a11 = ffma2(h1.y, C.whh[1][2 * c + 1], a11);
    }

    float s00 = hadd2(a00), s01 = hadd2(a01);
    float s10 = hadd2(a10), s11 = hadd2(a11);

    // butterfly-split reduce over the 4 kq lanes
    float g0 = C.odd1 ? s00 : s01;
    float g1 = C.odd1 ? s10 : s11;
    float r0 = __shfl_xor_sync(0xffffffffu, g0, 8);
    float r1 = __shfl_xor_sync(0xffffffffu, g1, 8);
    float u0 = (C.odd1 ? s01 : s00) + r0;   // (j0, b=kq&1)
    float u1 = (C.odd1 ? s11 : s10) + r1;   // (j1, b=kq&1)
    float g  = C.odd2 ? u0 : u1;
    float r  = __shfl_xor_sync(0xffffffffu, g, 16);
    float sF = (C.odd2 ? u1 : u0) + r;      // finished (j,b) for this lane

    hw[C.stoff] = tanh_ap(sF + C.biasF);
}

// Stage one 16-step x tile via cp.async (addresses recomputed, not cached).
__device__ __forceinline__ void stage_tile(
    const float* __restrict__ xg, int row0, int tid, unsigned sx0,
    int sbuf, int tile)
{
    #pragma unroll
    for (int r = 0; r < 2; r++) {
        int idx = tid + 256 * r;          // 0..511
        int bb  = idx >> 8;               // batch within CTA
        int rem = idx & 255;
        int tt  = rem >> 4, f4 = rem & 15;
        const float* src = xg + ((size_t)(row0 + bb) * TSTEPS + tile * 16 + tt) * IDIM + f4 * 4;
        unsigned dst = sx0 + (unsigned)sbuf * SX_BUF_BYTES
                     + (unsigned)(bb * SX_B_STRIDE + tt * XROW + (f4 >> 2) * 20 + (f4 & 3) * 4) * 4u;
        asm volatile("cp.async.cg.shared.global [%0], [%1], 16;"
                     :: "r"(dst), "l"(src) : "memory");
    }
}

__global__ void __launch_bounds__(256, 2) rnn_fused(
    const float* __restrict__ x,
    const float* __restrict__ W_ih,
    const float* __restrict__ W_hh,
    const float* __restrict__ b_ih,
    const float* __restrict__ b_hh,
    const float* __restrict__ fc_w,
    const float* __restrict__ fc_b,
    float* __restrict__ out)
{
    __shared__ __align__(16) float sx[2][2][16][XROW];   // 20 KB (double buffer)
    __shared__ __align__(16) float hbuf[2][2][HSTR];     // ping-pong h

    const int tid  = threadIdx.x;
    const int warp = tid >> 5, lane = tid & 31;
    const int kq   = lane >> 3;
    const int jl   = lane & 7;
    const int j0   = warp * 16 + jl;
    const int j1   = j0 + 8;
    const int row0 = blockIdx.x * 2;

    StepCtx C;
    C.kq36 = 36 * kq;
    C.kq20 = 20 * kq;
    C.odd1 = (kq & 1) != 0;
    C.odd2 = (kq & 2) != 0;
    {
        int jfin = (kq & 2) ? j1 : j0;
        int bfin = kq & 1;
        int jfp  = jfin + ((jfin >> 5) << 2);
        C.stoff  = bfin * HSTR + jfp;
        C.biasF  = b_ih[jfin] + b_hh[jfin];
    }

    // ---- load weights into registers ----
    #pragma unroll
    for (int jj = 0; jj < 2; jj++) {
        const float4* wr = (const float4*)(W_hh + (size_t)(jj ? j1 : j0) * HDIM + 32 * kq);
        #pragma unroll
        for (int c = 0; c < 8; c++) {
            float4 v = __ldg(wr + c);
            C.whh[jj][2 * c]     = pk(v.x, v.y);
            C.whh[jj][2 * c + 1] = pk(v.z, v.w);
        }
    }
    #pragma unroll
    for (int jj = 0; jj < 2; jj++) {
        const float4* wr = (const float4*)(W_ih + (size_t)(jj ? j1 : j0) * IDIM + 16 * kq);
        #pragma unroll
        for (int cc = 0; cc < 4; cc++) {
            float4 v = __ldg(wr + cc);
            C.wih[jj][2 * cc]     = pk(v.x, v.y);
            C.wih[jj][2 * cc + 1] = pk(v.z, v.w);
        }
    }

    // ---- zero h buffers ----
    for (int i = tid; i < 2 * 2 * HSTR; i += 256) (&hbuf[0][0][0])[i] = 0.f;

    const unsigned sx0 = (unsigned)__cvta_generic_to_shared(&sx[0][0][0][0]);

    // stage tile 0 into buffer 0
    stage_tile(x, row0, tid, sx0, 0, 0);
    asm volatile("cp.async.commit_group;" ::: "memory");
    asm volatile("cp.async.wait_group 0;" ::: "memory");
    __syncthreads();

    float* hA = &hbuf[0][0][0];
    float* hB = &hbuf[1][0][0];

    u64t acc[4];
    xseed(C, &sx[0][0][0][0], acc);   // x partials for t = 0

    int s = 0;
    #pragma unroll 1
    for (int tile = 0; tile < TSTEPS / 16; tile++) {
        // prefetch next tile into the other buffer
        if (tile + 1 < TSTEPS / 16)
            stage_tile(x, row0, tid, sx0, s ^ 1, tile + 1);
        asm volatile("cp.async.commit_group;" ::: "memory");

        const float* xb = &sx[s][0][0][0];

        // steps 0..13 in ping-pong pairs; xseed(t+1) fills the barrier drain
        #pragma unroll 1
        for (int m = 0; m < 7; m++) {
            const float* xu = xb + (2 * m + 1) * XROW;
            hstep(C, hA, hB, acc);
            BAR_ARRIVE();
            xseed(C, xu, acc);
            BAR_SYNC();
            hstep(C, hB, hA, acc);
            BAR_ARRIVE();
            xseed(C, xu + XROW, acc);
            BAR_SYNC();
        }
        // step 14: next x = x(15), same buffer
        hstep(C, hA, hB, acc);
        BAR_ARRIVE();
        xseed(C, xb + 15 * XROW, acc);
        BAR_SYNC();
        // step 15: next x lives in the other buffer — wait own cp.async,
        // barrier so ALL threads' staged data is visible, then seed.
        hstep(C, hB, hA, acc);
        asm volatile("cp.async.wait_group 0;" ::: "memory");
        BAR_ARRIVE();
        BAR_SYNC();
        if (tile + 1 < TSTEPS / 16)
            xseed(C, &sx[s ^ 1][0][0][0], acc);
        s ^= 1;
    }

    // 1024 steps (even) -> final h in hbuf[0]
    if (warp < 2) {
        const int b = warp;
        float sum = 0.f;
        #pragma unroll
        for (int i = lane; i < HDIM; i += 32)
            sum += hbuf[0][b][i + ((i >> 5) << 2)] * fc_w[i];
        #pragma unroll
        for (int o = 16; o > 0; o >>= 1) sum += __shfl_xor_sync(0xffffffffu, sum, o);
        if (lane == 0) out[row0 + b] = 1.f / (1.f + __expf(-(sum + fc_b[0])));
    }
}

// ---------------------------------------------------------------------------
extern "C" void kernel_launch(void* const* d_in, const int* in_sizes, int n_in,
                              void* d_out, int out_size)
{
    const float* x    = (const float*)d_in[0];
    const float* W_ih = (const float*)d_in[1];
    const float* W_hh = (const float*)d_in[2];
    const float* b_ih = (const float*)d_in[3];
    const float* b_hh = (const float*)d_in[4];
    const float* fc_w = (const float*)d_in[5];
    const float* fc_b = (const float*)d_in[6];
    float* out = (float*)d_out;

    rnn_fused<<<BATCH / 2, 256>>>(x, W_ih, W_hh, b_ih, b_hh, fc_w, fc_b, out);
}

// round 13
// speedup vs baseline: 1.2404x; 1.1190x over previous
#include <cuda_runtime.h>
#include <cuda_bf16.h>
#include <cstdint>

#define BATCH 512
#define TSTEPS 1024
#define IDIM 64
#define HDIM 128
#define NB 8                        // batches per CTA (= mma N)
#define NCTA (BATCH / NB)           // 64 CTAs
#define TILE_T 8                    // steps per x staging tile
#define KCH 12                      // 8 h-chunks + 4 x-chunks of k16

// Pre-split x, packed in the exact B-fragment word layout:
// per (cta, t): 576 words = [split(2)][b(8)][36 words], row stride 36 words
// (36 mod 32 = 4 -> B-frag LDS bank = 4b+q, conflict-free).
__device__ uint32_t g_xprep[(size_t)NCTA * TSTEPS * 576];

__device__ __forceinline__ float tanh_ap(float x) {
    float y; asm("tanh.approx.f32 %0, %1;" : "=f"(y) : "f"(x)); return y;
}
__device__ __forceinline__ uint32_t pk2(float v0, float v1) {
    __nv_bfloat162 t = __floats2bfloat162_rn(v0, v1);   // .x = v0 (low half)
    return *(uint32_t*)&t;
}
// m16n8k16 row.col f32.bf16.bf16.f32 — baseline PTX (sm_80+), no 'a' needed.
__device__ __forceinline__ void mma_bf16(float* c, const uint32_t* a,
                                         uint32_t b0, uint32_t b1) {
    asm volatile(
        "mma.sync.aligned.m16n8k16.row.col.f32.bf16.bf16.f32 "
        "{%0,%1,%2,%3}, {%4,%5,%6,%7}, {%8,%9}, {%0,%1,%2,%3};"
        : "+f"(c[0]), "+f"(c[1]), "+f"(c[2]), "+f"(c[3])
        : "r"(a[0]), "r"(a[1]), "r"(a[2]), "r"(a[3]), "r"(b0), "r"(b1));
}
__device__ __forceinline__ uint32_t smem_u32(const void* p) {
    uint32_t a;
    asm("{ .reg .u64 t; cvta.to.shared.u64 t, %1; cvt.u32.u64 %0, t; }" : "=r"(a) : "l"(p));
    return a;
}
#define CPASYNC16(d, s) asm volatile("cp.async.cg.shared.global [%0], [%1], 16;" :: "r"(d), "l"(s) : "memory")
#define CP_COMMIT()     asm volatile("cp.async.commit_group;" ::: "memory")
#define CP_WAIT0()      asm volatile("cp.async.wait_group 0;" ::: "memory")

// ---------------------------------------------------------------------------
// Prep: split x into bf16 hi/lo pairs, packed as B-operand words.
// One warp per (cta, t); lane handles i = 2*lane, 2*lane+1.
// ---------------------------------------------------------------------------
__global__ void xprep_kernel(const float* __restrict__ x) {
    int gw   = (blockIdx.x * blockDim.x + threadIdx.x) >> 5;
    int lane = threadIdx.x & 31;
    int nw   = (gridDim.x * blockDim.x) >> 5;
    for (int task = gw; task < NCTA * TSTEPS; task += nw) {
        int c = task >> 10;
        int t = task & 1023;
        uint32_t* outw = g_xprep + (size_t)task * 576;
        #pragma unroll
        for (int b = 0; b < NB; b++) {
            float2 v = *(const float2*)(x + ((size_t)(c * NB + b) * TSTEPS + t) * IDIM + 2 * lane);
            __nv_bfloat162 hi = __floats2bfloat162_rn(v.x, v.y);
            float l0 = v.x - __bfloat162float(hi.x);
            float l1 = v.y - __bfloat162float(hi.y);
            outw[b * 36 + lane]       = *(uint32_t*)&hi;      // hi split
            outw[288 + b * 36 + lane] = pk2(l0, l1);          // lo split
        }
    }
}

// ---------------------------------------------------------------------------
// Main: mma.sync recurrence. 64 CTAs x 256 threads (8 warps), 8 batches/CTA.
// Warp w owns j rows [16w, 16w+16): its A-fragments of W' = [W_hh | W_ih]
// (bf16 hi+lo) live in 96 registers, loaded once.
// Per step: z = Whi*vhi + Whi*vlo + Wlo*vhi via 36 HMMA (3 interleaved
// accumulator chains), B-frags from conflict-free shared; tanh epilogue
// writes h_hi/h_lo back into the B layout; one __syncthreads per step.
// h in shared: [ping][split][b][68 words] (68 mod 32 = 4 -> bank 4b+q).
// ---------------------------------------------------------------------------
__global__ void __launch_bounds__(256) rnn_mma(
    const float* __restrict__ W_ih,
    const float* __restrict__ W_hh,
    const float* __restrict__ b_ih,
    const float* __restrict__ b_hh,
    const float* __restrict__ fc_w,
    const float* __restrict__ fc_b,
    float* __restrict__ out)
{
    __shared__ uint32_t hsh[2][2][NB][68];            // 8704 B
    __shared__ uint32_t xsh[2][TILE_T][2][NB][36];    // 36864 B

    const int tid  = threadIdx.x;
    const int w    = tid >> 5, lane = tid & 31;
    const int q    = lane & 3;          // quad col
    const int rh   = lane >> 2;         // 0..7
    const int j0   = 16 * w + rh;       // accum rows j0, j0+8
    const int bN   = rh;                // B-frag batch col
    const int c    = blockIdx.x;

    // ---- A fragments (weights), hi + lo splits ----
    uint32_t wa[KCH][4], wl[KCH][4];
    #pragma unroll
    for (int kc = 0; kc < KCH; kc++) {
        #pragma unroll
        for (int rr = 0; rr < 4; rr++) {
            int row = j0 + (rr & 1) * 8;
            int col = kc * 16 + q * 2 + (rr >> 1) * 8;
            const float* src = (kc < 8) ? (W_hh + (size_t)row * HDIM + col)
                                        : (W_ih + (size_t)row * IDIM + (col - 128));
            float v0 = src[0], v1 = src[1];
            __nv_bfloat162 hi = __floats2bfloat162_rn(v0, v1);
            wa[kc][rr] = *(uint32_t*)&hi;
            wl[kc][rr] = pk2(v0 - __bfloat162float(hi.x), v1 - __bfloat162float(hi.y));
        }
    }
    const float bias_a = b_ih[j0] + b_hh[j0];
    const float bias_b = b_ih[j0 + 8] + b_hh[j0 + 8];

    // ---- h0 = 0 ----
    for (int i = tid; i < 2 * 2 * NB * 68; i += 256) (&hsh[0][0][0][0])[i] = 0;

    const uint32_t xs0 = smem_u32(&xsh[0][0][0][0][0]);

    // ---- stage x tile 0 ----
    {
        const uint32_t* src = g_xprep + (size_t)c * TSTEPS * 576;
        #pragma unroll
        for (int r = 0; r < 5; r++) {
            int idx = tid + 256 * r;
            if (idx < 1152) CPASYNC16(xs0 + idx * 16, src + idx * 4);
        }
    }
    CP_COMMIT();
    CP_WAIT0();
    __syncthreads();

    float h4[4] = {0.f, 0.f, 0.f, 0.f};
    int par = 0, sbuf = 0;

    #pragma unroll 1
    for (int tile = 0; tile < TSTEPS / TILE_T; tile++) {
        // prefetch next x tile
        if (tile + 1 < TSTEPS / TILE_T) {
            const uint32_t* src = g_xprep + ((size_t)c * TSTEPS + (tile + 1) * TILE_T) * 576;
            uint32_t dst = xs0 + (uint32_t)(sbuf ^ 1) * 18432u;
            #pragma unroll
            for (int r = 0; r < 5; r++) {
                int idx = tid + 256 * r;
                if (idx < 1152) CPASYNC16(dst + idx * 16, src + idx * 4);
            }
        }
        CP_COMMIT();

        #pragma unroll 1
        for (int u = 0; u < TILE_T; u++) {
            const uint32_t* hbH = &hsh[par][0][bN][0];
            const uint32_t* hbL = &hsh[par][1][bN][0];
            const uint32_t* xbH = &xsh[sbuf][u][0][bN][0];
            const uint32_t* xbL = &xsh[sbuf][u][1][bN][0];

            float a0[4] = {0.f, 0.f, 0.f, 0.f};   // Whi * vhi
            float a1[4] = {0.f, 0.f, 0.f, 0.f};   // Whi * vlo
            float a2[4] = {0.f, 0.f, 0.f, 0.f};   // Wlo * vhi
            #pragma unroll
            for (int kc = 0; kc < KCH; kc++) {
                uint32_t b0h, b1h, b0l, b1l;
                if (kc < 8) {
                    b0h = hbH[kc * 8 + q];  b1h = hbH[kc * 8 + q + 4];
                    b0l = hbL[kc * 8 + q];  b1l = hbL[kc * 8 + q + 4];
                } else {
                    int xc = kc - 8;
                    b0h = xbH[xc * 8 + q];  b1h = xbH[xc * 8 + q + 4];
                    b0l = xbL[xc * 8 + q];  b1l = xbL[xc * 8 + q + 4];
                }
                mma_bf16(a0, wa[kc], b0h, b1h);
                mma_bf16(a1, wa[kc], b0l, b1l);
                mma_bf16(a2, wl[kc], b0h, b1h);
            }

            h4[0] = tanh_ap(a0[0] + a1[0] + a2[0] + bias_a);
            h4[1] = tanh_ap(a0[1] + a1[1] + a2[1] + bias_a);
            h4[2] = tanh_ap(a0[2] + a1[2] + a2[2] + bias_b);
            h4[3] = tanh_ap(a0[3] + a1[3] + a2[3] + bias_b);

            // store h_{t+1} (hi/lo) into the other h buffer, B layout
            {
                uint16_t* dh = (uint16_t*)&hsh[par ^ 1][0][0][0];  // 136 halves/row
                uint16_t* dl = (uint16_t*)&hsh[par ^ 1][1][0][0];
                int n0 = 2 * q;
                #pragma unroll
                for (int e = 0; e < 4; e++) {
                    int jj = j0 + (e >> 1) * 8;
                    int nn = n0 + (e & 1);
                    __nv_bfloat16 hh = __float2bfloat16_rn(h4[e]);
                    __nv_bfloat16 hl = __float2bfloat16_rn(h4[e] - __bfloat162float(hh));
                    dh[nn * 136 + jj] = *(uint16_t*)&hh;
                    dl[nn * 136 + jj] = *(uint16_t*)&hl;
                }
            }
            __syncthreads();
            par ^= 1;
        }
        CP_WAIT0();
        __syncthreads();
        sbuf ^= 1;
    }

    // ---- fc + sigmoid epilogue (reuse x staging as fp32 scratch) ----
    {
        float* hf = (float*)xsh;                 // [n][132] floats
        int n0 = 2 * q;
        hf[n0 * 132 + j0]           = h4[0];
        hf[(n0 + 1) * 132 + j0]     = h4[1];
        hf[n0 * 132 + j0 + 8]       = h4[2];
        hf[(n0 + 1) * 132 + j0 + 8] = h4[3];
        __syncthreads();
        if (w < NB && tid < 256) {
            float sum = 0.f;
            #pragma unroll
            for (int i = lane; i < HDIM; i += 32)
                sum += hf[w * 132 + i] * fc_w[i];
            #pragma unroll
            for (int o = 16; o > 0; o >>= 1)
                sum += __shfl_xor_sync(0xffffffffu, sum, o);
            if (lane == 0)
                out[c * NB + w] = 1.f / (1.f + __expf(-(sum + fc_b[0])));
        }
    }
}

// ---------------------------------------------------------------------------
extern "C" void kernel_launch(void* const* d_in, const int* in_sizes, int n_in,
                              void* d_out, int out_size)
{
    const float* x    = (const float*)d_in[0];
    const float* W_ih = (const float*)d_in[1];
    const float* W_hh = (const float*)d_in[2];
    const float* b_ih = (const float*)d_in[3];
    const float* b_hh = (const float*)d_in[4];
    const float* fc_w = (const float*)d_in[5];
    const float* fc_b = (const float*)d_in[6];
    float* out = (float*)d_out;

    xprep_kernel<<<512, 256>>>(x);
    rnn_mma<<<NCTA, 256>>>(W_ih, W_hh, b_ih, b_hh, fc_w, fc_b, out);
}